// round 6
// baseline (speedup 1.0000x reference)
#include <cuda_runtime.h>
#include <cuda_bf16.h>
#include <math.h>

#define H      2048
#define NH     32
#define NKV    8
#define HD     64
#define GROUPS 4
#define FF     5632
#define BATCH  2
#define SEQ    2048
#define M_TOK  (BATCH*SEQ)
#define QKV_N  3072

#define ATTN_SMEM (4*64*68*4)
#define GEMM_SMEM 65536

// weight plane element offsets (Q,K,V contiguous -> fused QKV GEMM)
#define OFF_Q  ((size_t)0)
#define OFF_K  (OFF_Q + (size_t)2048*2048)
#define OFF_V  (OFF_K + (size_t)512*2048)
#define OFF_O  (OFF_V + (size_t)512*2048)
#define OFF_G  (OFF_O + (size_t)2048*2048)
#define OFF_U  (OFF_G + (size_t)5632*2048)
#define OFF_D  (OFF_U + (size_t)5632*2048)
#define W_TOTAL (OFF_D + (size_t)2048*5632)

// ---------------- scratch (device globals: allocation-guard safe) ----------------
__device__ float g_qkv[M_TOK*QKV_N];   // fused Q|K|V projection output (rope in-place)
__device__ float g_hidden[M_TOK*H];
__device__ float g_gate[M_TOK*FF];
__device__ __nv_bfloat16 g_xn_h[M_TOK*H];
__device__ __nv_bfloat16 g_xn_l[M_TOK*H];
__device__ __nv_bfloat16 g_ao_h[M_TOK*H];
__device__ __nv_bfloat16 g_ao_l[M_TOK*H];
__device__ __nv_bfloat16 g_act_h[M_TOK*FF];
__device__ __nv_bfloat16 g_act_l[M_TOK*FF];
__device__ __nv_bfloat16 g_w_h[W_TOTAL];
__device__ __nv_bfloat16 g_w_l[W_TOTAL];

// ---------------- helpers ----------------
__device__ __forceinline__ unsigned pack_bf2(float a, float b) {
    __nv_bfloat162 t = __floats2bfloat162_rn(a, b);
    return *(unsigned*)&t;
}
__device__ __forceinline__ void split1(float x, float& hi, float& lo) {
    __nv_bfloat16 hb = __float2bfloat16(x);
    hi = __bfloat162float(hb);
    lo = x - hi;
}
__device__ __forceinline__ unsigned long long dupf2(float a) {
    unsigned long long d;
    asm("mov.b64 %0, {%1, %1};" : "=l"(d) : "f"(a));
    return d;
}
#define FMA2(acc, a, b) \
    asm("fma.rn.f32x2 %0, %1, %2, %0;" : "+l"(acc) : "l"(a), "l"(b))
#define MUL2(acc, s) \
    asm("mul.rn.f32x2 %0, %0, %1;" : "+l"(acc) : "l"(s))

#define SW64(x) ((unsigned)(x) ^ ((((unsigned)(x)) >> 3) & 0x30u))

#define CPA16(dst, src) \
    asm volatile("cp.async.cg.shared.global [%0], [%1], 16;" :: "r"(dst), "l"(src))
#define CPCOMMIT() asm volatile("cp.async.commit_group;")
#define CPWAIT0()  asm volatile("cp.async.wait_group 0;")

#define LDSM4(r, a) \
    asm volatile("ldmatrix.sync.aligned.m8n8.x4.shared.b16 {%0,%1,%2,%3}, [%4];" \
                 : "=r"((r)[0]), "=r"((r)[1]), "=r"((r)[2]), "=r"((r)[3]) : "r"(a))

#define MMA_B16(c, a, b0v, b1v) \
    asm volatile("mma.sync.aligned.m16n8k16.row.col.f32.bf16.bf16.f32 " \
                 "{%0,%1,%2,%3},{%4,%5,%6,%7},{%8,%9},{%0,%1,%2,%3};" \
                 : "+f"((c)[0]), "+f"((c)[1]), "+f"((c)[2]), "+f"((c)[3]) \
                 : "r"((a)[0]), "r"((a)[1]), "r"((a)[2]), "r"((a)[3]), "r"(b0v), "r"(b1v))

// ---------------- weight binarize + bf16 hi/lo split prepass ----------------
__global__ void binsplit_kernel(const float* __restrict__ src,
                                __nv_bfloat16* __restrict__ dh,
                                __nv_bfloat16* __restrict__ dl,
                                const float* __restrict__ kkp, const float* __restrict__ aap) {
    const float kk = kkp[0], aa = aap[0];
    size_t i = ((size_t)blockIdx.x * 256 + threadIdx.x) * 4;
    float4 w = *(const float4*)(src + i);
    float v[4] = {w.x, w.y, w.z, w.w};
    float hv[4], lv[4];
    #pragma unroll
    for (int j = 0; j < 4; j++) {
        float b = aa * fminf(fmaxf(kk * v[j], -1.0f), 1.0f);
        split1(b, hv[j], lv[j]);
    }
    uint2 ph = {pack_bf2(hv[0], hv[1]), pack_bf2(hv[2], hv[3])};
    uint2 pl = {pack_bf2(lv[0], lv[1]), pack_bf2(lv[2], lv[3])};
    *(uint2*)(dh + i) = ph;
    *(uint2*)(dl + i) = pl;
}

// ---------------- RMSNorm -> bf16 hi/lo planes ----------------
__global__ void rmsnorm_kernel(const float* __restrict__ x, const float* __restrict__ w,
                               __nv_bfloat16* __restrict__ yh, __nv_bfloat16* __restrict__ yl) {
    int row = blockIdx.x;
    const float4* xr = (const float4*)(x + (size_t)row * H);
    const float4* wv = (const float4*)w;
    int tid = threadIdx.x;
    float4 a = xr[tid];
    float4 b = xr[tid + 256];
    float ss = a.x*a.x + a.y*a.y + a.z*a.z + a.w*a.w
             + b.x*b.x + b.y*b.y + b.z*b.z + b.w*b.w;
    #pragma unroll
    for (int o = 16; o; o >>= 1) ss += __shfl_xor_sync(0xffffffffu, ss, o);
    __shared__ float ws[8];
    if ((tid & 31) == 0) ws[tid >> 5] = ss;
    __syncthreads();
    float tot = ws[0]+ws[1]+ws[2]+ws[3]+ws[4]+ws[5]+ws[6]+ws[7];
    float r = rsqrtf(tot * (1.0f / (float)H) + 1e-5f);
    float4 w0 = wv[tid], w1 = wv[tid + 256];
    float o0[4] = {a.x*r*w0.x, a.y*r*w0.y, a.z*r*w0.z, a.w*r*w0.w};
    float o1[4] = {b.x*r*w1.x, b.y*r*w1.y, b.z*r*w1.z, b.w*r*w1.w};
    float h0[4], l0[4], h1[4], l1[4];
    #pragma unroll
    for (int j = 0; j < 4; j++) { split1(o0[j], h0[j], l0[j]); split1(o1[j], h1[j], l1[j]); }
    size_t base = (size_t)row * H + 4 * tid;
    *(uint2*)(yh + base)        = make_uint2(pack_bf2(h0[0],h0[1]), pack_bf2(h0[2],h0[3]));
    *(uint2*)(yl + base)        = make_uint2(pack_bf2(l0[0],l0[1]), pack_bf2(l0[2],l0[3]));
    *(uint2*)(yh + base + 1024) = make_uint2(pack_bf2(h1[0],h1[1]), pack_bf2(h1[2],h1[3]));
    *(uint2*)(yl + base + 1024) = make_uint2(pack_bf2(l1[0],l1[1]), pack_bf2(l1[2],l1[3]));
}

// ---------------- tensor-core GEMM: ldmatrix + cp.async, bf16 hi/lo split ----------------
// C[M,N] = A @ W^T, A = Ah+Al, W = Wh+Wl, 3 MMA passes (HH, HL, LH).
// MODE 0: C fp32. MODE 1: C = acc + X. MODE 2: silu(X)*acc -> (Ch,Cl) planes.
template<int MODE>
__global__ void __launch_bounds__(256) gemm_mma(
    const __nv_bfloat16* __restrict__ Ah, const __nv_bfloat16* __restrict__ Al,
    const __nv_bfloat16* __restrict__ Wh, const __nv_bfloat16* __restrict__ Wl,
    const float* __restrict__ X, float* __restrict__ C,
    __nv_bfloat16* __restrict__ Ch, __nv_bfloat16* __restrict__ Cl,
    int N, int K)
{
    extern __shared__ unsigned char smem[];
    unsigned sbase = (unsigned)__cvta_generic_to_shared(smem);

    int tid = threadIdx.x;
    int bm = blockIdx.y << 7, bn = blockIdx.x << 7;

    int r0 = tid >> 2, c0 = tid & 3;
    const __nv_bfloat16* pAh0 = Ah + (size_t)(bm + r0) * K + c0 * 8;
    const __nv_bfloat16* pAh1 = Ah + (size_t)(bm + r0 + 64) * K + c0 * 8;
    const __nv_bfloat16* pAl0 = Al + (size_t)(bm + r0) * K + c0 * 8;
    const __nv_bfloat16* pAl1 = Al + (size_t)(bm + r0 + 64) * K + c0 * 8;
    const __nv_bfloat16* pWh0 = Wh + (size_t)(bn + r0) * K + c0 * 8;
    const __nv_bfloat16* pWh1 = Wh + (size_t)(bn + r0 + 64) * K + c0 * 8;
    const __nv_bfloat16* pWl0 = Wl + (size_t)(bn + r0) * K + c0 * 8;
    const __nv_bfloat16* pWl1 = Wl + (size_t)(bn + r0 + 64) * K + c0 * 8;
    unsigned dOff = SW64(64 * r0 + 16 * c0);

    int warp = tid >> 5, lane = tid & 31;
    int m0 = (warp & 1) << 6;
    int n0 = (warp >> 1) << 5;
    int lr = lane & 15;
    int lc = lane >> 4;
    unsigned aOff[4], bOff[2];
    #pragma unroll
    for (int i = 0; i < 4; i++) aOff[i] = 64u * (m0 + 16 * i + lr) + 16u * lc;
    #pragma unroll
    for (int j = 0; j < 2; j++) bOff[j] = 64u * (n0 + 16 * j + lr) + 16u * lc;

    int fr = lane >> 2, kp = lane & 3;

    float acc[4][4][4];
    #pragma unroll
    for (int i = 0; i < 4; i++)
        #pragma unroll
        for (int j = 0; j < 4; j++)
            #pragma unroll
            for (int r = 0; r < 4; r++) acc[i][j][r] = 0.0f;

    int nk = K >> 5;

    {
        unsigned b0 = sbase;
        CPA16(b0 + dOff,          pAh0);
        CPA16(b0 + dOff + 4096,   pAh1);
        CPA16(b0 + 8192  + dOff,        pAl0);
        CPA16(b0 + 8192  + dOff + 4096, pAl1);
        CPA16(b0 + 16384 + dOff,        pWh0);
        CPA16(b0 + 16384 + dOff + 4096, pWh1);
        CPA16(b0 + 24576 + dOff,        pWl0);
        CPA16(b0 + 24576 + dOff + 4096, pWl1);
        CPCOMMIT();
    }

    for (int kb = 0; kb < nk; kb++) {
        CPWAIT0();
        __syncthreads();
        if (kb + 1 < nk) {
            int ko = (kb + 1) << 5;
            unsigned b0 = sbase + (((kb + 1) & 1) << 15);
            CPA16(b0 + dOff,          pAh0 + ko);
            CPA16(b0 + dOff + 4096,   pAh1 + ko);
            CPA16(b0 + 8192  + dOff,        pAl0 + ko);
            CPA16(b0 + 8192  + dOff + 4096, pAl1 + ko);
            CPA16(b0 + 16384 + dOff,        pWh0 + ko);
            CPA16(b0 + 16384 + dOff + 4096, pWh1 + ko);
            CPA16(b0 + 24576 + dOff,        pWl0 + ko);
            CPA16(b0 + 24576 + dOff + 4096, pWl1 + ko);
            CPCOMMIT();
        }

        unsigned bAh = sbase + ((kb & 1) << 15);
        unsigned bAl = bAh + 8192, bWh = bAh + 16384, bWl = bAh + 24576;

        #pragma unroll
        for (int s = 0; s < 2; s++) {
            unsigned so = s << 5;
            unsigned aH[4][4], aL[4][4], bH[2][4], bL[2][4];
            #pragma unroll
            for (int i = 0; i < 4; i++) LDSM4(aH[i], bAh + SW64(aOff[i] + so));
            #pragma unroll
            for (int j = 0; j < 2; j++) LDSM4(bH[j], bWh + SW64(bOff[j] + so));
            #pragma unroll
            for (int i = 0; i < 4; i++)
                #pragma unroll
                for (int j = 0; j < 2; j++) {
                    MMA_B16(acc[i][2*j],   aH[i], bH[j][0], bH[j][2]);
                    MMA_B16(acc[i][2*j+1], aH[i], bH[j][1], bH[j][3]);
                }
            #pragma unroll
            for (int j = 0; j < 2; j++) LDSM4(bL[j], bWl + SW64(bOff[j] + so));
            #pragma unroll
            for (int i = 0; i < 4; i++)
                #pragma unroll
                for (int j = 0; j < 2; j++) {
                    MMA_B16(acc[i][2*j],   aH[i], bL[j][0], bL[j][2]);
                    MMA_B16(acc[i][2*j+1], aH[i], bL[j][1], bL[j][3]);
                }
            #pragma unroll
            for (int i = 0; i < 4; i++) LDSM4(aL[i], bAl + SW64(aOff[i] + so));
            #pragma unroll
            for (int i = 0; i < 4; i++)
                #pragma unroll
                for (int j = 0; j < 2; j++) {
                    MMA_B16(acc[i][2*j],   aL[i], bH[j][0], bH[j][2]);
                    MMA_B16(acc[i][2*j+1], aL[i], bH[j][1], bH[j][3]);
                }
        }
        __syncthreads();
    }

    #pragma unroll
    for (int i = 0; i < 4; i++) {
        #pragma unroll
        for (int j = 0; j < 4; j++) {
            int row0 = bm + m0 + 16 * i + fr;
            int col  = bn + n0 + 8 * j + kp * 2;
            #pragma unroll
            for (int half = 0; half < 2; half++) {
                int row = row0 + half * 8;
                float v0 = acc[i][j][2 * half + 0];
                float v1 = acc[i][j][2 * half + 1];
                size_t off = (size_t)row * N + col;
                if (MODE == 0) {
                    *(float2*)(C + off) = make_float2(v0, v1);
                } else if (MODE == 1) {
                    float2 xr = *(const float2*)(X + off);
                    *(float2*)(C + off) = make_float2(v0 + xr.x, v1 + xr.y);
                } else {
                    float2 gr = *(const float2*)(X + off);
                    v0 *= gr.x / (1.0f + expf(-gr.x));
                    v1 *= gr.y / (1.0f + expf(-gr.y));
                    float h0, l0, h1, l1;
                    split1(v0, h0, l0);
                    split1(v1, h1, l1);
                    *(unsigned*)(Ch + off) = pack_bf2(h0, h1);
                    *(unsigned*)(Cl + off) = pack_bf2(l0, l1);
                }
            }
        }
    }
}

// ---------------- RoPE (in-place on fused qkv buffer) ----------------
__global__ void rope_kernel(const int* __restrict__ pos_ids) {
    int gid = blockIdx.x * blockDim.x + threadIdx.x;
    int d = gid & 31;
    int slot = gid >> 5;
    int head = slot % (NH + NKV);
    int tok = slot / (NH + NKV);
    if (tok >= M_TOK) return;
    float p = (float)pos_ids[tok];
    float inv = powf(10000.0f, -(float)d * (1.0f / 32.0f));
    float ang = p * inv;
    float s, c;
    sincosf(ang, &s, &c);
    float* base;
    if (head < NH) base = g_qkv + (size_t)tok * QKV_N + (head << 6);
    else           base = g_qkv + (size_t)tok * QKV_N + 2048 + ((head - NH) << 6);
    float x1 = base[d];
    float x2 = base[d + 32];
    base[d]      = x1 * c - x2 * s;
    base[d + 32] = x2 * c + x1 * s;
}

// ---------------- Flash attention (causal, GQA) -> bf16 hi/lo planes ----------------
__global__ void __launch_bounds__(256, 1) attn_kernel() {
    extern __shared__ float sm[];
    float* Qt  = sm;
    float* KtT = sm + 64 * 68;
    float* Vt  = sm + 2 * 64 * 68;
    float* St  = sm + 3 * 64 * 68;

    int qt = blockIdx.x, h = blockIdx.y, b = blockIdx.z;
    int kh = h >> 2;
    int tid = threadIdx.x;

    for (int i = tid; i < 1024; i += 256) {
        int r = i >> 4, c4 = (i & 15) << 2;
        const float* src = g_qkv + (size_t)(b * SEQ + (qt << 6) + r) * QKV_N + (h << 6) + c4;
        float4 qv = *(const float4*)src;
        float* dst = &Qt[r * 68 + c4];
        dst[0] = qv.x * 0.125f; dst[1] = qv.y * 0.125f;
        dst[2] = qv.z * 0.125f; dst[3] = qv.w * 0.125f;
    }

    int qr = tid >> 2, qc = tid & 3;
    int pi = tid >> 4, pj = tid & 15;
    int qr0 = pi << 2, kc0 = pj << 2;

    unsigned long long acc2[8];
    #pragma unroll
    for (int d = 0; d < 8; d++) acc2[d] = 0ull;
    float mrow = -INFINITY, lrow = 0.0f;

    for (int kt = 0; kt <= qt; kt++) {
        __syncthreads();
        int tokbase = b * SEQ + (kt << 6);
        for (int i = tid; i < 1024; i += 256) {
            int r = i & 63, c4 = (i >> 6) << 2;
            const float* src = g_qkv + (size_t)(tokbase + r) * QKV_N + 2048 + (kh << 6) + c4;
            float4 kv = *(const float4*)src;
            KtT[(c4 + 0) * 68 + r] = kv.x;
            KtT[(c4 + 1) * 68 + r] = kv.y;
            KtT[(c4 + 2) * 68 + r] = kv.z;
            KtT[(c4 + 3) * 68 + r] = kv.w;
        }
        for (int i = tid; i < 1024; i += 256) {
            int r = i >> 4, c4 = (i & 15) << 2;
            const float* src = g_qkv + (size_t)(tokbase + r) * QKV_N + 2560 + (kh << 6) + c4;
            *(float4*)&Vt[r * 68 + c4] = *(const float4*)src;
        }
        __syncthreads();

        // phase A: S = (Q/8) K^T, packed f32x2 over kc pairs
        unsigned long long sacc2[4][2];
        #pragma unroll
        for (int i = 0; i < 4; i++) { sacc2[i][0] = 0ull; sacc2[i][1] = 0ull; }
        #pragma unroll
        for (int d4 = 0; d4 < 64; d4 += 4) {
            float4 aq[4];
            ulonglong2 bk[4];
            #pragma unroll
            for (int i = 0; i < 4; i++)
                aq[i] = *(const float4*)&Qt[(qr0 + i) * 68 + d4];
            #pragma unroll
            for (int dd = 0; dd < 4; dd++)
                bk[dd] = *(const ulonglong2*)&KtT[(d4 + dd) * 68 + kc0];
            #pragma unroll
            for (int i = 0; i < 4; i++) {
                unsigned long long a0 = dupf2(aq[i].x);
                unsigned long long a1 = dupf2(aq[i].y);
                unsigned long long a2 = dupf2(aq[i].z);
                unsigned long long a3 = dupf2(aq[i].w);
                FMA2(sacc2[i][0], a0, bk[0].x); FMA2(sacc2[i][1], a0, bk[0].y);
                FMA2(sacc2[i][0], a1, bk[1].x); FMA2(sacc2[i][1], a1, bk[1].y);
                FMA2(sacc2[i][0], a2, bk[2].x); FMA2(sacc2[i][1], a2, bk[2].y);
                FMA2(sacc2[i][0], a3, bk[3].x); FMA2(sacc2[i][1], a3, bk[3].y);
            }
        }
        bool diag = (kt == qt);
        #pragma unroll
        for (int i = 0; i < 4; i++) {
            int qg = (qt << 6) + qr0 + i;
            float2 p0 = *reinterpret_cast<float2*>(&sacc2[i][0]);
            float2 p1 = *reinterpret_cast<float2*>(&sacc2[i][1]);
            float v0 = p0.x, v1 = p0.y, v2 = p1.x, v3 = p1.y;
            if (diag) {
                int kg = (kt << 6) + kc0;
                if (kg + 0 > qg) v0 = -INFINITY;
                if (kg + 1 > qg) v1 = -INFINITY;
                if (kg + 2 > qg) v2 = -INFINITY;
                if (kg + 3 > qg) v3 = -INFINITY;
            }
            float4 r; r.x = v0; r.y = v1; r.z = v2; r.w = v3;
            *(float4*)&St[(qr0 + i) * 68 + kc0] = r;
        }
        __syncthreads();

        // phase B: online softmax (4 lanes per row)
        float* srow = &St[qr * 68 + (qc << 4)];
        float tmax = -INFINITY;
        #pragma unroll
        for (int j = 0; j < 16; j++) tmax = fmaxf(tmax, srow[j]);
        tmax = fmaxf(tmax, __shfl_xor_sync(0xffffffffu, tmax, 1));
        tmax = fmaxf(tmax, __shfl_xor_sync(0xffffffffu, tmax, 2));
        float mnew = fmaxf(mrow, tmax);
        float corr = __expf(mrow - mnew);
        float psum = 0.0f;
        #pragma unroll
        for (int j = 0; j < 16; j++) {
            float pv = __expf(srow[j] - mnew);
            srow[j] = pv;
            psum += pv;
        }
        psum += __shfl_xor_sync(0xffffffffu, psum, 1);
        psum += __shfl_xor_sync(0xffffffffu, psum, 2);
        lrow = lrow * corr + psum;
        mrow = mnew;
        unsigned long long c2 = dupf2(corr);
        #pragma unroll
        for (int d = 0; d < 8; d++) MUL2(acc2[d], c2);
        __syncwarp();

        // phase C: acc += P V, packed f32x2
        for (int kc = 0; kc < 64; kc++) {
            unsigned long long pv2 = dupf2(St[qr * 68 + kc]);
            const ulonglong2 w0 = *(const ulonglong2*)&Vt[kc * 68 + (qc << 4) + 0];
            const ulonglong2 w1 = *(const ulonglong2*)&Vt[kc * 68 + (qc << 4) + 4];
            const ulonglong2 w2 = *(const ulonglong2*)&Vt[kc * 68 + (qc << 4) + 8];
            const ulonglong2 w3 = *(const ulonglong2*)&Vt[kc * 68 + (qc << 4) + 12];
            FMA2(acc2[0], pv2, w0.x); FMA2(acc2[1], pv2, w0.y);
            FMA2(acc2[2], pv2, w1.x); FMA2(acc2[3], pv2, w1.y);
            FMA2(acc2[4], pv2, w2.x); FMA2(acc2[5], pv2, w2.y);
            FMA2(acc2[6], pv2, w3.x); FMA2(acc2[7], pv2, w3.y);
        }
    }

    // epilogue: normalize + bf16 hi/lo split -> planes for o-proj
    float inv_l = 1.0f / lrow;
    float o[16], oh[16], ol[16];
    #pragma unroll
    for (int d = 0; d < 8; d++) {
        float2 p = *reinterpret_cast<float2*>(&acc2[d]);
        o[2*d]   = p.x * inv_l;
        o[2*d+1] = p.y * inv_l;
    }
    #pragma unroll
    for (int d = 0; d < 16; d++) split1(o[d], oh[d], ol[d]);
    size_t idx = (((size_t)(b * SEQ + (qt << 6) + qr) * NH + h) << 6) + (qc << 4);
    uint4 ph0 = make_uint4(pack_bf2(oh[0],oh[1]), pack_bf2(oh[2],oh[3]),
                           pack_bf2(oh[4],oh[5]), pack_bf2(oh[6],oh[7]));
    uint4 ph1 = make_uint4(pack_bf2(oh[8],oh[9]), pack_bf2(oh[10],oh[11]),
                           pack_bf2(oh[12],oh[13]), pack_bf2(oh[14],oh[15]));
    uint4 pl0 = make_uint4(pack_bf2(ol[0],ol[1]), pack_bf2(ol[2],ol[3]),
                           pack_bf2(ol[4],ol[5]), pack_bf2(ol[6],ol[7]));
    uint4 pl1 = make_uint4(pack_bf2(ol[8],ol[9]), pack_bf2(ol[10],ol[11]),
                           pack_bf2(ol[12],ol[13]), pack_bf2(ol[14],ol[15]));
    *(uint4*)(g_ao_h + idx)     = ph0;
    *(uint4*)(g_ao_h + idx + 8) = ph1;
    *(uint4*)(g_ao_l + idx)     = pl0;
    *(uint4*)(g_ao_l + idx + 8) = pl1;
}

// ---------------- launch ----------------
extern "C" void kernel_launch(void* const* d_in, const int* in_sizes, int n_in,
                              void* d_out, int out_size) {
    (void)in_sizes; (void)n_in; (void)out_size;
    const float* hs     = (const float*)d_in[0];
    const int*   pos    = (const int*)d_in[2];
    const float* q_w    = (const float*)d_in[3];
    const float* k_w    = (const float*)d_in[4];
    const float* v_w    = (const float*)d_in[5];
    const float* o_w    = (const float*)d_in[6];
    const float* gate_w = (const float*)d_in[7];
    const float* up_w   = (const float*)d_in[8];
    const float* down_w = (const float*)d_in[9];
    const float* ln1    = (const float*)d_in[10];
    const float* ln2    = (const float*)d_in[11];
    const float* kkp    = (const float*)d_in[12];
    const float* aap    = (const float*)d_in[13];
    float* out = (float*)d_out;

    float *qkv, *hid, *gate;
    __nv_bfloat16 *xnh, *xnl, *aoh, *aol, *acth, *actl, *wh, *wl;
    cudaGetSymbolAddress((void**)&qkv,  g_qkv);
    cudaGetSymbolAddress((void**)&hid,  g_hidden);
    cudaGetSymbolAddress((void**)&gate, g_gate);
    cudaGetSymbolAddress((void**)&xnh,  g_xn_h);
    cudaGetSymbolAddress((void**)&xnl,  g_xn_l);
    cudaGetSymbolAddress((void**)&aoh,  g_ao_h);
    cudaGetSymbolAddress((void**)&aol,  g_ao_l);
    cudaGetSymbolAddress((void**)&acth, g_act_h);
    cudaGetSymbolAddress((void**)&actl, g_act_l);
    cudaGetSymbolAddress((void**)&wh,   g_w_h);
    cudaGetSymbolAddress((void**)&wl,   g_w_l);

    cudaFuncSetAttribute(attn_kernel, cudaFuncAttributeMaxDynamicSharedMemorySize, ATTN_SMEM);
    cudaFuncSetAttribute(gemm_mma<0>, cudaFuncAttributeMaxDynamicSharedMemorySize, GEMM_SMEM);
    cudaFuncSetAttribute(gemm_mma<1>, cudaFuncAttributeMaxDynamicSharedMemorySize, GEMM_SMEM);
    cudaFuncSetAttribute(gemm_mma<2>, cudaFuncAttributeMaxDynamicSharedMemorySize, GEMM_SMEM);

    dim3 blk(256);

    // 0) weight prepass: binarize + bf16 split (Q,K,V planes contiguous)
    binsplit_kernel<<<(2048*2048)/1024, blk>>>(q_w,    wh + OFF_Q, wl + OFF_Q, kkp, aap);
    binsplit_kernel<<<(512*2048)/1024,  blk>>>(k_w,    wh + OFF_K, wl + OFF_K, kkp, aap);
    binsplit_kernel<<<(512*2048)/1024,  blk>>>(v_w,    wh + OFF_V, wl + OFF_V, kkp, aap);
    binsplit_kernel<<<(2048*2048)/1024, blk>>>(o_w,    wh + OFF_O, wl + OFF_O, kkp, aap);
    binsplit_kernel<<<(5632*2048)/1024, blk>>>(gate_w, wh + OFF_G, wl + OFF_G, kkp, aap);
    binsplit_kernel<<<(5632*2048)/1024, blk>>>(up_w,   wh + OFF_U, wl + OFF_U, kkp, aap);
    binsplit_kernel<<<(2048*5632)/1024, blk>>>(down_w, wh + OFF_D, wl + OFF_D, kkp, aap);

    // 1) rmsnorm 1 -> planes
    rmsnorm_kernel<<<M_TOK, blk>>>(hs, ln1, xnh, xnl);
    // 2) fused QKV projection (N = 3072)
    gemm_mma<0><<<dim3(QKV_N/128, M_TOK/128), blk, GEMM_SMEM>>>(xnh, xnl, wh+OFF_Q, wl+OFF_Q, nullptr, qkv, nullptr, nullptr, QKV_N, H);
    // 3) rope
    rope_kernel<<<(M_TOK*(NH+NKV)*32)/256, blk>>>(pos);
    // 4) attention -> ao planes
    attn_kernel<<<dim3(SEQ/64, NH, BATCH), blk, ATTN_SMEM>>>();
    // 5) o-proj + residual
    gemm_mma<1><<<dim3(H/128, M_TOK/128), blk, GEMM_SMEM>>>(aoh, aol, wh+OFF_O, wl+OFF_O, hs, hid, nullptr, nullptr, H, H);
    // 6) rmsnorm 2 -> planes
    rmsnorm_kernel<<<M_TOK, blk>>>(hid, ln2, xnh, xnl);
    // 7) gate proj (fp32 out)
    gemm_mma<0><<<dim3(FF/128, M_TOK/128), blk, GEMM_SMEM>>>(xnh, xnl, wh+OFF_G, wl+OFF_G, nullptr, gate, nullptr, nullptr, FF, H);
    // 8) up proj, fused silu(gate)*up -> act planes
    gemm_mma<2><<<dim3(FF/128, M_TOK/128), blk, GEMM_SMEM>>>(xnh, xnl, wh+OFF_U, wl+OFF_U, gate, nullptr, acth, actl, FF, H);
    // 9) down proj + residual -> out
    gemm_mma<1><<<dim3(H/128, M_TOK/128), blk, GEMM_SMEM>>>(acth, actl, wh+OFF_D, wl+OFF_D, hid, out, nullptr, nullptr, H, FF);
}

// round 7
// speedup vs baseline: 1.5433x; 1.5433x over previous
#include <cuda_runtime.h>
#include <cuda_bf16.h>
#include <math.h>

#define H      2048
#define NH     32
#define NKV    8
#define HD     64
#define GROUPS 4
#define FF     5632
#define BATCH  2
#define SEQ    2048
#define M_TOK  (BATCH*SEQ)
#define QKV_N  3072

#define ATTN_SMEM 83456
#define GEMM_SMEM 65536

// weight plane element offsets (Q,K,V contiguous -> fused QKV GEMM)
#define OFF_Q  ((size_t)0)
#define OFF_K  (OFF_Q + (size_t)2048*2048)
#define OFF_V  (OFF_K + (size_t)512*2048)
#define OFF_O  (OFF_V + (size_t)512*2048)
#define OFF_G  (OFF_O + (size_t)2048*2048)
#define OFF_U  (OFF_G + (size_t)5632*2048)
#define OFF_D  (OFF_U + (size_t)5632*2048)
#define W_TOTAL (OFF_D + (size_t)2048*5632)

// ---------------- scratch (device globals: allocation-guard safe) ----------------
__device__ float g_qkv[M_TOK*QKV_N];
__device__ float g_hidden[M_TOK*H];
__device__ float g_gate[M_TOK*FF];
__device__ __nv_bfloat16 g_xn_h[M_TOK*H];
__device__ __nv_bfloat16 g_xn_l[M_TOK*H];
__device__ __nv_bfloat16 g_ao_h[M_TOK*H];
__device__ __nv_bfloat16 g_ao_l[M_TOK*H];
__device__ __nv_bfloat16 g_act_h[M_TOK*FF];
__device__ __nv_bfloat16 g_act_l[M_TOK*FF];
__device__ __nv_bfloat16 g_w_h[W_TOTAL];
__device__ __nv_bfloat16 g_w_l[W_TOTAL];

// ---------------- helpers ----------------
__device__ __forceinline__ unsigned pack_bf2(float a, float b) {
    __nv_bfloat162 t = __floats2bfloat162_rn(a, b);
    return *(unsigned*)&t;
}
__device__ __forceinline__ void split1(float x, float& hi, float& lo) {
    __nv_bfloat16 hb = __float2bfloat16(x);
    hi = __bfloat162float(hb);
    lo = x - hi;
}

#define SW64(x)   ((unsigned)(x) ^ ((((unsigned)(x)) >> 3) & 0x30u))
#define SW128X(x) ((unsigned)(x) ^ ((((unsigned)(x)) >> 3) & 0x70u))

#define CPA16(dst, src) \
    asm volatile("cp.async.cg.shared.global [%0], [%1], 16;" :: "r"(dst), "l"(src))
#define CPCOMMIT() asm volatile("cp.async.commit_group;")
#define CPWAIT0()  asm volatile("cp.async.wait_group 0;")

#define LDSM4(r, a) \
    asm volatile("ldmatrix.sync.aligned.m8n8.x4.shared.b16 {%0,%1,%2,%3}, [%4];" \
                 : "=r"((r)[0]), "=r"((r)[1]), "=r"((r)[2]), "=r"((r)[3]) : "r"(a))
#define LDSM4T(r, a) \
    asm volatile("ldmatrix.sync.aligned.m8n8.x4.trans.shared.b16 {%0,%1,%2,%3}, [%4];" \
                 : "=r"((r)[0]), "=r"((r)[1]), "=r"((r)[2]), "=r"((r)[3]) : "r"(a))

#define MMA_B16(c, a, b0v, b1v) \
    asm volatile("mma.sync.aligned.m16n8k16.row.col.f32.bf16.bf16.f32 " \
                 "{%0,%1,%2,%3},{%4,%5,%6,%7},{%8,%9},{%0,%1,%2,%3};" \
                 : "+f"((c)[0]), "+f"((c)[1]), "+f"((c)[2]), "+f"((c)[3]) \
                 : "r"((a)[0]), "r"((a)[1]), "r"((a)[2]), "r"((a)[3]), "r"(b0v), "r"(b1v))

// ---------------- weight binarize + bf16 hi/lo split prepass ----------------
__global__ void binsplit_kernel(const float* __restrict__ src,
                                __nv_bfloat16* __restrict__ dh,
                                __nv_bfloat16* __restrict__ dl,
                                const float* __restrict__ kkp, const float* __restrict__ aap) {
    const float kk = kkp[0], aa = aap[0];
    size_t i = ((size_t)blockIdx.x * 256 + threadIdx.x) * 4;
    float4 w = *(const float4*)(src + i);
    float v[4] = {w.x, w.y, w.z, w.w};
    float hv[4], lv[4];
    #pragma unroll
    for (int j = 0; j < 4; j++) {
        float b = aa * fminf(fmaxf(kk * v[j], -1.0f), 1.0f);
        split1(b, hv[j], lv[j]);
    }
    *(uint2*)(dh + i) = make_uint2(pack_bf2(hv[0], hv[1]), pack_bf2(hv[2], hv[3]));
    *(uint2*)(dl + i) = make_uint2(pack_bf2(lv[0], lv[1]), pack_bf2(lv[2], lv[3]));
}

// ---------------- RMSNorm -> bf16 hi/lo planes ----------------
__global__ void rmsnorm_kernel(const float* __restrict__ x, const float* __restrict__ w,
                               __nv_bfloat16* __restrict__ yh, __nv_bfloat16* __restrict__ yl) {
    int row = blockIdx.x;
    const float4* xr = (const float4*)(x + (size_t)row * H);
    const float4* wv = (const float4*)w;
    int tid = threadIdx.x;
    float4 a = xr[tid];
    float4 b = xr[tid + 256];
    float ss = a.x*a.x + a.y*a.y + a.z*a.z + a.w*a.w
             + b.x*b.x + b.y*b.y + b.z*b.z + b.w*b.w;
    #pragma unroll
    for (int o = 16; o; o >>= 1) ss += __shfl_xor_sync(0xffffffffu, ss, o);
    __shared__ float ws[8];
    if ((tid & 31) == 0) ws[tid >> 5] = ss;
    __syncthreads();
    float tot = ws[0]+ws[1]+ws[2]+ws[3]+ws[4]+ws[5]+ws[6]+ws[7];
    float r = rsqrtf(tot * (1.0f / (float)H) + 1e-5f);
    float4 w0 = wv[tid], w1 = wv[tid + 256];
    float o0[4] = {a.x*r*w0.x, a.y*r*w0.y, a.z*r*w0.z, a.w*r*w0.w};
    float o1[4] = {b.x*r*w1.x, b.y*r*w1.y, b.z*r*w1.z, b.w*r*w1.w};
    float h0[4], l0[4], h1[4], l1[4];
    #pragma unroll
    for (int j = 0; j < 4; j++) { split1(o0[j], h0[j], l0[j]); split1(o1[j], h1[j], l1[j]); }
    size_t base = (size_t)row * H + 4 * tid;
    *(uint2*)(yh + base)        = make_uint2(pack_bf2(h0[0],h0[1]), pack_bf2(h0[2],h0[3]));
    *(uint2*)(yl + base)        = make_uint2(pack_bf2(l0[0],l0[1]), pack_bf2(l0[2],l0[3]));
    *(uint2*)(yh + base + 1024) = make_uint2(pack_bf2(h1[0],h1[1]), pack_bf2(h1[2],h1[3]));
    *(uint2*)(yl + base + 1024) = make_uint2(pack_bf2(l1[0],l1[1]), pack_bf2(l1[2],l1[3]));
}

// ---------------- tensor-core GEMM: ldmatrix + cp.async, bf16 hi/lo split ----------------
template<int MODE>
__global__ void __launch_bounds__(256) gemm_mma(
    const __nv_bfloat16* __restrict__ Ah, const __nv_bfloat16* __restrict__ Al,
    const __nv_bfloat16* __restrict__ Wh, const __nv_bfloat16* __restrict__ Wl,
    const float* __restrict__ X, float* __restrict__ C,
    __nv_bfloat16* __restrict__ Ch, __nv_bfloat16* __restrict__ Cl,
    int N, int K)
{
    extern __shared__ unsigned char smem[];
    unsigned sbase = (unsigned)__cvta_generic_to_shared(smem);

    int tid = threadIdx.x;
    int bm = blockIdx.y << 7, bn = blockIdx.x << 7;

    int r0 = tid >> 2, c0 = tid & 3;
    const __nv_bfloat16* pAh0 = Ah + (size_t)(bm + r0) * K + c0 * 8;
    const __nv_bfloat16* pAh1 = Ah + (size_t)(bm + r0 + 64) * K + c0 * 8;
    const __nv_bfloat16* pAl0 = Al + (size_t)(bm + r0) * K + c0 * 8;
    const __nv_bfloat16* pAl1 = Al + (size_t)(bm + r0 + 64) * K + c0 * 8;
    const __nv_bfloat16* pWh0 = Wh + (size_t)(bn + r0) * K + c0 * 8;
    const __nv_bfloat16* pWh1 = Wh + (size_t)(bn + r0 + 64) * K + c0 * 8;
    const __nv_bfloat16* pWl0 = Wl + (size_t)(bn + r0) * K + c0 * 8;
    const __nv_bfloat16* pWl1 = Wl + (size_t)(bn + r0 + 64) * K + c0 * 8;
    unsigned dOff = SW64(64 * r0 + 16 * c0);

    int warp = tid >> 5, lane = tid & 31;
    int m0 = (warp & 1) << 6;
    int n0 = (warp >> 1) << 5;
    int lr = lane & 15;
    int lc = lane >> 4;
    unsigned aOff[4], bOff[2];
    #pragma unroll
    for (int i = 0; i < 4; i++) aOff[i] = 64u * (m0 + 16 * i + lr) + 16u * lc;
    #pragma unroll
    for (int j = 0; j < 2; j++) bOff[j] = 64u * (n0 + 16 * j + lr) + 16u * lc;

    int fr = lane >> 2, kp = lane & 3;

    float acc[4][4][4];
    #pragma unroll
    for (int i = 0; i < 4; i++)
        #pragma unroll
        for (int j = 0; j < 4; j++)
            #pragma unroll
            for (int r = 0; r < 4; r++) acc[i][j][r] = 0.0f;

    int nk = K >> 5;

    {
        unsigned b0 = sbase;
        CPA16(b0 + dOff,          pAh0);
        CPA16(b0 + dOff + 4096,   pAh1);
        CPA16(b0 + 8192  + dOff,        pAl0);
        CPA16(b0 + 8192  + dOff + 4096, pAl1);
        CPA16(b0 + 16384 + dOff,        pWh0);
        CPA16(b0 + 16384 + dOff + 4096, pWh1);
        CPA16(b0 + 24576 + dOff,        pWl0);
        CPA16(b0 + 24576 + dOff + 4096, pWl1);
        CPCOMMIT();
    }

    for (int kb = 0; kb < nk; kb++) {
        CPWAIT0();
        __syncthreads();
        if (kb + 1 < nk) {
            int ko = (kb + 1) << 5;
            unsigned b0 = sbase + (((kb + 1) & 1) << 15);
            CPA16(b0 + dOff,          pAh0 + ko);
            CPA16(b0 + dOff + 4096,   pAh1 + ko);
            CPA16(b0 + 8192  + dOff,        pAl0 + ko);
            CPA16(b0 + 8192  + dOff + 4096, pAl1 + ko);
            CPA16(b0 + 16384 + dOff,        pWh0 + ko);
            CPA16(b0 + 16384 + dOff + 4096, pWh1 + ko);
            CPA16(b0 + 24576 + dOff,        pWl0 + ko);
            CPA16(b0 + 24576 + dOff + 4096, pWl1 + ko);
            CPCOMMIT();
        }

        unsigned bAh = sbase + ((kb & 1) << 15);
        unsigned bAl = bAh + 8192, bWh = bAh + 16384, bWl = bAh + 24576;

        #pragma unroll
        for (int s = 0; s < 2; s++) {
            unsigned so = s << 5;
            unsigned aH[4][4], aL[4][4], bH[2][4], bL[2][4];
            #pragma unroll
            for (int i = 0; i < 4; i++) LDSM4(aH[i], bAh + SW64(aOff[i] + so));
            #pragma unroll
            for (int j = 0; j < 2; j++) LDSM4(bH[j], bWh + SW64(bOff[j] + so));
            #pragma unroll
            for (int i = 0; i < 4; i++)
                #pragma unroll
                for (int j = 0; j < 2; j++) {
                    MMA_B16(acc[i][2*j],   aH[i], bH[j][0], bH[j][2]);
                    MMA_B16(acc[i][2*j+1], aH[i], bH[j][1], bH[j][3]);
                }
            #pragma unroll
            for (int j = 0; j < 2; j++) LDSM4(bL[j], bWl + SW64(bOff[j] + so));
            #pragma unroll
            for (int i = 0; i < 4; i++)
                #pragma unroll
                for (int j = 0; j < 2; j++) {
                    MMA_B16(acc[i][2*j],   aH[i], bL[j][0], bL[j][2]);
                    MMA_B16(acc[i][2*j+1], aH[i], bL[j][1], bL[j][3]);
                }
            #pragma unroll
            for (int i = 0; i < 4; i++) LDSM4(aL[i], bAl + SW64(aOff[i] + so));
            #pragma unroll
            for (int i = 0; i < 4; i++)
                #pragma unroll
                for (int j = 0; j < 2; j++) {
                    MMA_B16(acc[i][2*j],   aL[i], bH[j][0], bH[j][2]);
                    MMA_B16(acc[i][2*j+1], aL[i], bH[j][1], bH[j][3]);
                }
        }
        __syncthreads();
    }

    #pragma unroll
    for (int i = 0; i < 4; i++) {
        #pragma unroll
        for (int j = 0; j < 4; j++) {
            int row0 = bm + m0 + 16 * i + fr;
            int col  = bn + n0 + 8 * j + kp * 2;
            #pragma unroll
            for (int half = 0; half < 2; half++) {
                int row = row0 + half * 8;
                float v0 = acc[i][j][2 * half + 0];
                float v1 = acc[i][j][2 * half + 1];
                size_t off = (size_t)row * N + col;
                if (MODE == 0) {
                    *(float2*)(C + off) = make_float2(v0, v1);
                } else if (MODE == 1) {
                    float2 xr = *(const float2*)(X + off);
                    *(float2*)(C + off) = make_float2(v0 + xr.x, v1 + xr.y);
                } else {
                    float2 gr = *(const float2*)(X + off);
                    v0 *= gr.x / (1.0f + expf(-gr.x));
                    v1 *= gr.y / (1.0f + expf(-gr.y));
                    float h0, l0, h1, l1;
                    split1(v0, h0, l0);
                    split1(v1, h1, l1);
                    *(unsigned*)(Ch + off) = pack_bf2(h0, h1);
                    *(unsigned*)(Cl + off) = pack_bf2(l0, l1);
                }
            }
        }
    }
}

// ---------------- RoPE (in-place on fused qkv buffer) ----------------
__global__ void rope_kernel(const int* __restrict__ pos_ids) {
    int gid = blockIdx.x * blockDim.x + threadIdx.x;
    int d = gid & 31;
    int slot = gid >> 5;
    int head = slot % (NH + NKV);
    int tok = slot / (NH + NKV);
    if (tok >= M_TOK) return;
    float p = (float)pos_ids[tok];
    float inv = powf(10000.0f, -(float)d * (1.0f / 32.0f));
    float ang = p * inv;
    float s, c;
    sincosf(ang, &s, &c);
    float* base;
    if (head < NH) base = g_qkv + (size_t)tok * QKV_N + (head << 6);
    else           base = g_qkv + (size_t)tok * QKV_N + 2048 + ((head - NH) << 6);
    float x1 = base[d];
    float x2 = base[d + 32];
    base[d]      = x1 * c - x2 * s;
    base[d + 32] = x2 * c + x1 * s;
}

// ---------------- Tensor-core flash attention (causal, GQA) -> bf16 hi/lo planes ----------------
// S = QK^T via mma (bf16 split, 3-pass), scalar online softmax, O += PV via mma
// (P split, V via ldmatrix.trans). O accum in fp32 mma registers.
__global__ void __launch_bounds__(256, 2) attn_kernel() {
    extern __shared__ unsigned char smn[];
    unsigned sb = (unsigned)__cvta_generic_to_shared(smn);
    const unsigned QhO = 0,     QlO = 8192,  KhO = 16384, KlO = 24576;
    const unsigned VhO = 32768, VlO = 40960, PhO = 49152, PlO = 57344;
    float* St   = (float*)(smn + 65536);    // 64 x 68 fp32
    float* corr = (float*)(smn + 82944);    // 64
    float* linv = (float*)(smn + 83200);    // 64

    int qt = blockIdx.x, h = blockIdx.y, b = blockIdx.z;
    int kh = h >> 2;
    int tid = threadIdx.x, warp = tid >> 5, lane = tid & 31;
    int m0 = (warp >> 1) << 4;   // 0,16,32,48 (q-stripe)
    int n0 = (warp & 1) << 5;    // 0,32 (col half)
    int lr = lane & 15, lc = lane >> 4;
    int fr = lane >> 2, kp = lane & 3;
    int qr = tid >> 2, qc = tid & 3;

    // Q load: scale by 1/8, split to bf16 planes (SW128 layout, 128B rows)
    for (int i = tid; i < 1024; i += 256) {
        int r = i >> 4, c4 = (i & 15) << 2;
        const float* src = g_qkv + (size_t)(b*SEQ + (qt<<6) + r)*QKV_N + (h<<6) + c4;
        float4 q = *(const float4*)src;
        float h0,l0,h1,l1,h2,l2,h3,l3;
        split1(q.x*0.125f,h0,l0); split1(q.y*0.125f,h1,l1);
        split1(q.z*0.125f,h2,l2); split1(q.w*0.125f,h3,l3);
        unsigned off = SW128X(r*128 + c4*2);
        *(uint2*)(smn + QhO + off) = make_uint2(pack_bf2(h0,h1), pack_bf2(h2,h3));
        *(uint2*)(smn + QlO + off) = make_uint2(pack_bf2(l0,l1), pack_bf2(l2,l3));
    }

    float oacc[4][4];
    #pragma unroll
    for (int j = 0; j < 4; j++)
        #pragma unroll
        for (int r = 0; r < 4; r++) oacc[j][r] = 0.0f;
    float mrow = -INFINITY, lrow = 0.0f;

    for (int kt = 0; kt <= qt; kt++) {
        __syncthreads();   // previous phase C done (K/V/P reusable)
        int tokbase = b*SEQ + (kt<<6);
        for (int i = tid; i < 1024; i += 256) {
            int r = i >> 4, c4 = (i & 15) << 2;
            const float* ksrc = g_qkv + (size_t)(tokbase + r)*QKV_N + 2048 + (kh<<6) + c4;
            float4 kv = *(const float4*)ksrc;
            float4 vv = *(const float4*)(ksrc + 512);
            unsigned off = SW128X(r*128 + c4*2);
            float h0,l0,h1,l1,h2,l2,h3,l3;
            split1(kv.x,h0,l0); split1(kv.y,h1,l1); split1(kv.z,h2,l2); split1(kv.w,h3,l3);
            *(uint2*)(smn + KhO + off) = make_uint2(pack_bf2(h0,h1), pack_bf2(h2,h3));
            *(uint2*)(smn + KlO + off) = make_uint2(pack_bf2(l0,l1), pack_bf2(l2,l3));
            split1(vv.x,h0,l0); split1(vv.y,h1,l1); split1(vv.z,h2,l2); split1(vv.w,h3,l3);
            *(uint2*)(smn + VhO + off) = make_uint2(pack_bf2(h0,h1), pack_bf2(h2,h3));
            *(uint2*)(smn + VlO + off) = make_uint2(pack_bf2(l0,l1), pack_bf2(l2,l3));
        }
        __syncthreads();

        // phase A: S = Q K^T (3-pass split)
        float accS[4][4];
        #pragma unroll
        for (int j = 0; j < 4; j++)
            #pragma unroll
            for (int r = 0; r < 4; r++) accS[j][r] = 0.0f;
        #pragma unroll
        for (int ks = 0; ks < 4; ks++) {
            unsigned co = 32*ks + 16*lc;
            unsigned aoff = SW128X((m0 + lr)*128 + co);
            unsigned ah[4], al[4];
            LDSM4(ah, sb + QhO + aoff);
            LDSM4(al, sb + QlO + aoff);
            #pragma unroll
            for (int j2 = 0; j2 < 2; j2++) {
                unsigned boff = SW128X((n0 + 16*j2 + lr)*128 + co);
                unsigned bh[4], bl[4];
                LDSM4(bh, sb + KhO + boff);
                LDSM4(bl, sb + KlO + boff);
                MMA_B16(accS[2*j2],   ah, bh[0], bh[2]);
                MMA_B16(accS[2*j2+1], ah, bh[1], bh[3]);
                MMA_B16(accS[2*j2],   ah, bl[0], bl[2]);
                MMA_B16(accS[2*j2+1], ah, bl[1], bl[3]);
                MMA_B16(accS[2*j2],   al, bh[0], bh[2]);
                MMA_B16(accS[2*j2+1], al, bh[1], bh[3]);
            }
        }
        bool diag = (kt == qt);
        #pragma unroll
        for (int j = 0; j < 4; j++) {
            int col = n0 + 8*j + 2*kp;
            #pragma unroll
            for (int hf = 0; hf < 2; hf++) {
                int row = m0 + fr + 8*hf;
                float v0 = accS[j][2*hf], v1 = accS[j][2*hf+1];
                if (diag) {
                    if (col > row)     v0 = -INFINITY;
                    if (col + 1 > row) v1 = -INFINITY;
                }
                *(float2*)&St[row*68 + col] = make_float2(v0, v1);
            }
        }
        __syncthreads();

        // phase B: scalar online softmax (row qr, 4 lanes)
        float* srow = &St[qr*68 + (qc<<4)];
        float tmax = -INFINITY;
        #pragma unroll
        for (int j = 0; j < 16; j++) tmax = fmaxf(tmax, srow[j]);
        tmax = fmaxf(tmax, __shfl_xor_sync(0xffffffffu, tmax, 1));
        tmax = fmaxf(tmax, __shfl_xor_sync(0xffffffffu, tmax, 2));
        float mnew = fmaxf(mrow, tmax);
        float cv = __expf(mrow - mnew);
        float psum = 0.0f;
        float pv[16];
        #pragma unroll
        for (int j = 0; j < 16; j++) { pv[j] = __expf(srow[j] - mnew); psum += pv[j]; }
        psum += __shfl_xor_sync(0xffffffffu, psum, 1);
        psum += __shfl_xor_sync(0xffffffffu, psum, 2);
        lrow = lrow * cv + psum;
        mrow = mnew;
        if (qc == 0) corr[qr] = cv;
        #pragma unroll
        for (int p = 0; p < 8; p++) {
            float hh0, ll0, hh1, ll1;
            split1(pv[2*p],   hh0, ll0);
            split1(pv[2*p+1], hh1, ll1);
            unsigned off = SW128X(qr*128 + qc*32 + p*4);
            *(unsigned*)(smn + PhO + off) = pack_bf2(hh0, hh1);
            *(unsigned*)(smn + PlO + off) = pack_bf2(ll0, ll1);
        }
        __syncthreads();

        // phase C: O = O*corr + P V (3-pass split, V via ldmatrix.trans)
        float c0v = corr[m0 + fr], c1v = corr[m0 + fr + 8];
        #pragma unroll
        for (int j = 0; j < 4; j++) {
            oacc[j][0] *= c0v; oacc[j][1] *= c0v;
            oacc[j][2] *= c1v; oacc[j][3] *= c1v;
        }
        #pragma unroll
        for (int ks = 0; ks < 4; ks++) {
            unsigned co = 32*ks + 16*lc;
            unsigned aoff = SW128X((m0 + lr)*128 + co);
            unsigned ph[4], pl[4];
            LDSM4(ph, sb + PhO + aoff);
            LDSM4(pl, sb + PlO + aoff);
            #pragma unroll
            for (int j2 = 0; j2 < 2; j2++) {
                unsigned boff = SW128X((16*ks + lr)*128 + (n0 + 16*j2)*2 + 16*lc);
                unsigned bh[4], bl[4];
                LDSM4T(bh, sb + VhO + boff);
                LDSM4T(bl, sb + VlO + boff);
                MMA_B16(oacc[2*j2],   ph, bh[0], bh[1]);
                MMA_B16(oacc[2*j2+1], ph, bh[2], bh[3]);
                MMA_B16(oacc[2*j2],   ph, bl[0], bl[1]);
                MMA_B16(oacc[2*j2+1], ph, bl[2], bl[3]);
                MMA_B16(oacc[2*j2],   pl, bh[0], bh[1]);
                MMA_B16(oacc[2*j2+1], pl, bh[2], bh[3]);
            }
        }
    }

    if (qc == 0) linv[qr] = 1.0f / lrow;
    __syncthreads();
    float i0 = linv[m0 + fr], i1 = linv[m0 + fr + 8];
    #pragma unroll
    for (int j = 0; j < 4; j++) {
        int d = n0 + 8*j + 2*kp;
        #pragma unroll
        for (int hf = 0; hf < 2; hf++) {
            int row = m0 + fr + 8*hf;
            float sc = hf ? i1 : i0;
            float v0 = oacc[j][2*hf] * sc, v1 = oacc[j][2*hf+1] * sc;
            float h0, l0, h1, l1;
            split1(v0, h0, l0);
            split1(v1, h1, l1);
            size_t idx = (((size_t)(b*SEQ + (qt<<6) + row)*NH + h) << 6) + d;
            *(unsigned*)(g_ao_h + idx) = pack_bf2(h0, h1);
            *(unsigned*)(g_ao_l + idx) = pack_bf2(l0, l1);
        }
    }
}

// ---------------- launch ----------------
extern "C" void kernel_launch(void* const* d_in, const int* in_sizes, int n_in,
                              void* d_out, int out_size) {
    (void)in_sizes; (void)n_in; (void)out_size;
    const float* hs     = (const float*)d_in[0];
    const int*   pos    = (const int*)d_in[2];
    const float* q_w    = (const float*)d_in[3];
    const float* k_w    = (const float*)d_in[4];
    const float* v_w    = (const float*)d_in[5];
    const float* o_w    = (const float*)d_in[6];
    const float* gate_w = (const float*)d_in[7];
    const float* up_w   = (const float*)d_in[8];
    const float* down_w = (const float*)d_in[9];
    const float* ln1    = (const float*)d_in[10];
    const float* ln2    = (const float*)d_in[11];
    const float* kkp    = (const float*)d_in[12];
    const float* aap    = (const float*)d_in[13];
    float* out = (float*)d_out;

    float *qkv, *hid, *gate;
    __nv_bfloat16 *xnh, *xnl, *aoh, *aol, *acth, *actl, *wh, *wl;
    cudaGetSymbolAddress((void**)&qkv,  g_qkv);
    cudaGetSymbolAddress((void**)&hid,  g_hidden);
    cudaGetSymbolAddress((void**)&gate, g_gate);
    cudaGetSymbolAddress((void**)&xnh,  g_xn_h);
    cudaGetSymbolAddress((void**)&xnl,  g_xn_l);
    cudaGetSymbolAddress((void**)&aoh,  g_ao_h);
    cudaGetSymbolAddress((void**)&aol,  g_ao_l);
    cudaGetSymbolAddress((void**)&acth, g_act_h);
    cudaGetSymbolAddress((void**)&actl, g_act_l);
    cudaGetSymbolAddress((void**)&wh,   g_w_h);
    cudaGetSymbolAddress((void**)&wl,   g_w_l);

    cudaFuncSetAttribute(attn_kernel, cudaFuncAttributeMaxDynamicSharedMemorySize, ATTN_SMEM);
    cudaFuncSetAttribute(gemm_mma<0>, cudaFuncAttributeMaxDynamicSharedMemorySize, GEMM_SMEM);
    cudaFuncSetAttribute(gemm_mma<1>, cudaFuncAttributeMaxDynamicSharedMemorySize, GEMM_SMEM);
    cudaFuncSetAttribute(gemm_mma<2>, cudaFuncAttributeMaxDynamicSharedMemorySize, GEMM_SMEM);

    dim3 blk(256);

    // 0) weight prepass: binarize + bf16 split (Q,K,V planes contiguous)
    binsplit_kernel<<<(2048*2048)/1024, blk>>>(q_w,    wh + OFF_Q, wl + OFF_Q, kkp, aap);
    binsplit_kernel<<<(512*2048)/1024,  blk>>>(k_w,    wh + OFF_K, wl + OFF_K, kkp, aap);
    binsplit_kernel<<<(512*2048)/1024,  blk>>>(v_w,    wh + OFF_V, wl + OFF_V, kkp, aap);
    binsplit_kernel<<<(2048*2048)/1024, blk>>>(o_w,    wh + OFF_O, wl + OFF_O, kkp, aap);
    binsplit_kernel<<<(5632*2048)/1024, blk>>>(gate_w, wh + OFF_G, wl + OFF_G, kkp, aap);
    binsplit_kernel<<<(5632*2048)/1024, blk>>>(up_w,   wh + OFF_U, wl + OFF_U, kkp, aap);
    binsplit_kernel<<<(2048*5632)/1024, blk>>>(down_w, wh + OFF_D, wl + OFF_D, kkp, aap);

    // 1) rmsnorm 1 -> planes
    rmsnorm_kernel<<<M_TOK, blk>>>(hs, ln1, xnh, xnl);
    // 2) fused QKV projection (N = 3072)
    gemm_mma<0><<<dim3(QKV_N/128, M_TOK/128), blk, GEMM_SMEM>>>(xnh, xnl, wh+OFF_Q, wl+OFF_Q, nullptr, qkv, nullptr, nullptr, QKV_N, H);
    // 3) rope
    rope_kernel<<<(M_TOK*(NH+NKV)*32)/256, blk>>>(pos);
    // 4) attention -> ao planes
    attn_kernel<<<dim3(SEQ/64, NH, BATCH), blk, ATTN_SMEM>>>();
    // 5) o-proj + residual
    gemm_mma<1><<<dim3(H/128, M_TOK/128), blk, GEMM_SMEM>>>(aoh, aol, wh+OFF_O, wl+OFF_O, hs, hid, nullptr, nullptr, H, H);
    // 6) rmsnorm 2 -> planes
    rmsnorm_kernel<<<M_TOK, blk>>>(hid, ln2, xnh, xnl);
    // 7) gate proj (fp32 out)
    gemm_mma<0><<<dim3(FF/128, M_TOK/128), blk, GEMM_SMEM>>>(xnh, xnl, wh+OFF_G, wl+OFF_G, nullptr, gate, nullptr, nullptr, FF, H);
    // 8) up proj, fused silu(gate)*up -> act planes
    gemm_mma<2><<<dim3(FF/128, M_TOK/128), blk, GEMM_SMEM>>>(xnh, xnl, wh+OFF_U, wl+OFF_U, gate, nullptr, acth, actl, FF, H);
    // 9) down proj + residual -> out
    gemm_mma<1><<<dim3(H/128, M_TOK/128), blk, GEMM_SMEM>>>(acth, actl, wh+OFF_D, wl+OFF_D, hid, out, nullptr, nullptr, H, FF);
}

// round 8
// speedup vs baseline: 1.7716x; 1.1480x over previous
#include <cuda_runtime.h>
#include <cuda_bf16.h>
#include <math.h>

#define H      2048
#define NH     32
#define NKV    8
#define HD     64
#define GROUPS 4
#define FF     5632
#define BATCH  2
#define SEQ    2048
#define M_TOK  (BATCH*SEQ)
#define QKV_N  3072

#define ATTN_SMEM 83456
#define GEMM_SMEM 65536

// weight plane element offsets (Q,K,V contiguous -> fused QKV GEMM)
#define OFF_Q  ((size_t)0)
#define OFF_K  (OFF_Q + (size_t)2048*2048)
#define OFF_V  (OFF_K + (size_t)512*2048)
#define OFF_O  (OFF_V + (size_t)512*2048)
#define OFF_G  (OFF_O + (size_t)2048*2048)
#define OFF_U  (OFF_G + (size_t)5632*2048)
#define OFF_D  (OFF_U + (size_t)5632*2048)
#define W_TOTAL (OFF_D + (size_t)2048*5632)

// ---------------- scratch (device globals: allocation-guard safe) ----------------
__device__ float g_qkv[M_TOK*QKV_N];
__device__ float g_hidden[M_TOK*H];
__device__ float g_gate[M_TOK*FF];
__device__ __nv_bfloat16 g_xn_h[M_TOK*H];
__device__ __nv_bfloat16 g_xn_l[M_TOK*H];
__device__ __nv_bfloat16 g_ao_h[M_TOK*H];
__device__ __nv_bfloat16 g_ao_l[M_TOK*H];
__device__ __nv_bfloat16 g_act_h[M_TOK*FF];
__device__ __nv_bfloat16 g_act_l[M_TOK*FF];
__device__ __nv_bfloat16 g_w_h[W_TOTAL];
__device__ __nv_bfloat16 g_w_l[W_TOTAL];

// ---------------- helpers ----------------
__device__ __forceinline__ unsigned pack_bf2(float a, float b) {
    __nv_bfloat162 t = __floats2bfloat162_rn(a, b);
    return *(unsigned*)&t;
}
__device__ __forceinline__ void split1(float x, float& hi, float& lo) {
    __nv_bfloat16 hb = __float2bfloat16(x);
    hi = __bfloat162float(hb);
    lo = x - hi;
}

#define SW64(x)   ((unsigned)(x) ^ ((((unsigned)(x)) >> 3) & 0x30u))
#define SW128X(x) ((unsigned)(x) ^ ((((unsigned)(x)) >> 3) & 0x70u))

#define CPA16(dst, src) \
    asm volatile("cp.async.cg.shared.global [%0], [%1], 16;" :: "r"(dst), "l"(src))
#define CPCOMMIT() asm volatile("cp.async.commit_group;")
#define CPWAIT0()  asm volatile("cp.async.wait_group 0;")

#define LDSM4(r, a) \
    asm volatile("ldmatrix.sync.aligned.m8n8.x4.shared.b16 {%0,%1,%2,%3}, [%4];" \
                 : "=r"((r)[0]), "=r"((r)[1]), "=r"((r)[2]), "=r"((r)[3]) : "r"(a))
#define LDSM4T(r, a) \
    asm volatile("ldmatrix.sync.aligned.m8n8.x4.trans.shared.b16 {%0,%1,%2,%3}, [%4];" \
                 : "=r"((r)[0]), "=r"((r)[1]), "=r"((r)[2]), "=r"((r)[3]) : "r"(a))

#define MMA_B16(c, a, b0v, b1v) \
    asm volatile("mma.sync.aligned.m16n8k16.row.col.f32.bf16.bf16.f32 " \
                 "{%0,%1,%2,%3},{%4,%5,%6,%7},{%8,%9},{%0,%1,%2,%3};" \
                 : "+f"((c)[0]), "+f"((c)[1]), "+f"((c)[2]), "+f"((c)[3]) \
                 : "r"((a)[0]), "r"((a)[1]), "r"((a)[2]), "r"((a)[3]), "r"(b0v), "r"(b1v))

// ---------------- weight binarize + bf16 hi/lo split prepass ----------------
__global__ void binsplit_kernel(const float* __restrict__ src,
                                __nv_bfloat16* __restrict__ dh,
                                __nv_bfloat16* __restrict__ dl,
                                const float* __restrict__ kkp, const float* __restrict__ aap) {
    const float kk = kkp[0], aa = aap[0];
    size_t i = ((size_t)blockIdx.x * 256 + threadIdx.x) * 4;
    float4 w = *(const float4*)(src + i);
    float v[4] = {w.x, w.y, w.z, w.w};
    float hv[4], lv[4];
    #pragma unroll
    for (int j = 0; j < 4; j++) {
        float b = aa * fminf(fmaxf(kk * v[j], -1.0f), 1.0f);
        split1(b, hv[j], lv[j]);
    }
    *(uint2*)(dh + i) = make_uint2(pack_bf2(hv[0], hv[1]), pack_bf2(hv[2], hv[3]));
    *(uint2*)(dl + i) = make_uint2(pack_bf2(lv[0], lv[1]), pack_bf2(lv[2], lv[3]));
}

// ---------------- RMSNorm -> bf16 hi/lo planes ----------------
__global__ void rmsnorm_kernel(const float* __restrict__ x, const float* __restrict__ w,
                               __nv_bfloat16* __restrict__ yh, __nv_bfloat16* __restrict__ yl) {
    int row = blockIdx.x;
    const float4* xr = (const float4*)(x + (size_t)row * H);
    const float4* wv = (const float4*)w;
    int tid = threadIdx.x;
    float4 a = xr[tid];
    float4 b = xr[tid + 256];
    float ss = a.x*a.x + a.y*a.y + a.z*a.z + a.w*a.w
             + b.x*b.x + b.y*b.y + b.z*b.z + b.w*b.w;
    #pragma unroll
    for (int o = 16; o; o >>= 1) ss += __shfl_xor_sync(0xffffffffu, ss, o);
    __shared__ float ws[8];
    if ((tid & 31) == 0) ws[tid >> 5] = ss;
    __syncthreads();
    float tot = ws[0]+ws[1]+ws[2]+ws[3]+ws[4]+ws[5]+ws[6]+ws[7];
    float r = rsqrtf(tot * (1.0f / (float)H) + 1e-5f);
    float4 w0 = wv[tid], w1 = wv[tid + 256];
    float o0[4] = {a.x*r*w0.x, a.y*r*w0.y, a.z*r*w0.z, a.w*r*w0.w};
    float o1[4] = {b.x*r*w1.x, b.y*r*w1.y, b.z*r*w1.z, b.w*r*w1.w};
    float h0[4], l0[4], h1[4], l1[4];
    #pragma unroll
    for (int j = 0; j < 4; j++) { split1(o0[j], h0[j], l0[j]); split1(o1[j], h1[j], l1[j]); }
    size_t base = (size_t)row * H + 4 * tid;
    *(uint2*)(yh + base)        = make_uint2(pack_bf2(h0[0],h0[1]), pack_bf2(h0[2],h0[3]));
    *(uint2*)(yl + base)        = make_uint2(pack_bf2(l0[0],l0[1]), pack_bf2(l0[2],l0[3]));
    *(uint2*)(yh + base + 1024) = make_uint2(pack_bf2(h1[0],h1[1]), pack_bf2(h1[2],h1[3]));
    *(uint2*)(yl + base + 1024) = make_uint2(pack_bf2(l1[0],l1[1]), pack_bf2(l1[2],l1[3]));
}

// ---------------- tensor-core GEMM: ldmatrix + cp.async, bf16 hi/lo split, 2 CTA/SM ----------------
template<int MODE>
__global__ void __launch_bounds__(256, 2) gemm_mma(
    const __nv_bfloat16* __restrict__ Ah, const __nv_bfloat16* __restrict__ Al,
    const __nv_bfloat16* __restrict__ Wh, const __nv_bfloat16* __restrict__ Wl,
    const float* __restrict__ X, float* __restrict__ C,
    __nv_bfloat16* __restrict__ Ch, __nv_bfloat16* __restrict__ Cl,
    int N, int K)
{
    extern __shared__ unsigned char smem[];
    unsigned sbase = (unsigned)__cvta_generic_to_shared(smem);

    int tid = threadIdx.x;
    int bm = blockIdx.y << 7, bn = blockIdx.x << 7;

    // staging: 2 base pointers + deltas (register thrift for 2 CTA/SM)
    int r0 = tid >> 2, c0 = tid & 3;
    const __nv_bfloat16* pA = Ah + (size_t)(bm + r0) * K + c0 * 8;
    const __nv_bfloat16* pW = Wh + (size_t)(bn + r0) * K + c0 * 8;
    ptrdiff_t dAl = Al - Ah;
    ptrdiff_t dWl = Wl - Wh;
    ptrdiff_t d64 = (ptrdiff_t)64 * K;
    unsigned dOff = SW64(64 * r0 + 16 * c0);

    int warp = tid >> 5, lane = tid & 31;
    int m0 = (warp & 1) << 6;
    int n0 = (warp >> 1) << 5;
    int lr = lane & 15;
    int lc = lane >> 4;
    unsigned aOff[4], bOff[2];
    #pragma unroll
    for (int i = 0; i < 4; i++) aOff[i] = 64u * (m0 + 16 * i + lr) + 16u * lc;
    #pragma unroll
    for (int j = 0; j < 2; j++) bOff[j] = 64u * (n0 + 16 * j + lr) + 16u * lc;

    int fr = lane >> 2, kp = lane & 3;

    float acc[4][4][4];
    #pragma unroll
    for (int i = 0; i < 4; i++)
        #pragma unroll
        for (int j = 0; j < 4; j++)
            #pragma unroll
            for (int r = 0; r < 4; r++) acc[i][j][r] = 0.0f;

    int nk = K >> 5;

    {
        unsigned b0 = sbase;
        CPA16(b0 + dOff,                 pA);
        CPA16(b0 + dOff + 4096,          pA + d64);
        CPA16(b0 + 8192  + dOff,         pA + dAl);
        CPA16(b0 + 8192  + dOff + 4096,  pA + dAl + d64);
        CPA16(b0 + 16384 + dOff,         pW);
        CPA16(b0 + 16384 + dOff + 4096,  pW + d64);
        CPA16(b0 + 24576 + dOff,         pW + dWl);
        CPA16(b0 + 24576 + dOff + 4096,  pW + dWl + d64);
        CPCOMMIT();
    }

    for (int kb = 0; kb < nk; kb++) {
        CPWAIT0();
        __syncthreads();
        if (kb + 1 < nk) {
            int ko = (kb + 1) << 5;
            unsigned b0 = sbase + (((kb + 1) & 1) << 15);
            CPA16(b0 + dOff,                 pA + ko);
            CPA16(b0 + dOff + 4096,          pA + d64 + ko);
            CPA16(b0 + 8192  + dOff,         pA + dAl + ko);
            CPA16(b0 + 8192  + dOff + 4096,  pA + dAl + d64 + ko);
            CPA16(b0 + 16384 + dOff,         pW + ko);
            CPA16(b0 + 16384 + dOff + 4096,  pW + d64 + ko);
            CPA16(b0 + 24576 + dOff,         pW + dWl + ko);
            CPA16(b0 + 24576 + dOff + 4096,  pW + dWl + d64 + ko);
            CPCOMMIT();
        }

        unsigned bAh = sbase + ((kb & 1) << 15);
        unsigned bAl = bAh + 8192, bWh = bAh + 16384, bWl = bAh + 24576;

        #pragma unroll
        for (int s = 0; s < 2; s++) {
            unsigned so = s << 5;
            unsigned aH[4][4], aL[4][4], bH[2][4], bL[2][4];
            #pragma unroll
            for (int i = 0; i < 4; i++) LDSM4(aH[i], bAh + SW64(aOff[i] + so));
            #pragma unroll
            for (int j = 0; j < 2; j++) LDSM4(bH[j], bWh + SW64(bOff[j] + so));
            #pragma unroll
            for (int i = 0; i < 4; i++)
                #pragma unroll
                for (int j = 0; j < 2; j++) {
                    MMA_B16(acc[i][2*j],   aH[i], bH[j][0], bH[j][2]);
                    MMA_B16(acc[i][2*j+1], aH[i], bH[j][1], bH[j][3]);
                }
            #pragma unroll
            for (int j = 0; j < 2; j++) LDSM4(bL[j], bWl + SW64(bOff[j] + so));
            #pragma unroll
            for (int i = 0; i < 4; i++)
                #pragma unroll
                for (int j = 0; j < 2; j++) {
                    MMA_B16(acc[i][2*j],   aH[i], bL[j][0], bL[j][2]);
                    MMA_B16(acc[i][2*j+1], aH[i], bL[j][1], bL[j][3]);
                }
            #pragma unroll
            for (int i = 0; i < 4; i++) LDSM4(aL[i], bAl + SW64(aOff[i] + so));
            #pragma unroll
            for (int i = 0; i < 4; i++)
                #pragma unroll
                for (int j = 0; j < 2; j++) {
                    MMA_B16(acc[i][2*j],   aL[i], bH[j][0], bH[j][2]);
                    MMA_B16(acc[i][2*j+1], aL[i], bH[j][1], bH[j][3]);
                }
        }
        __syncthreads();
    }

    #pragma unroll
    for (int i = 0; i < 4; i++) {
        #pragma unroll
        for (int j = 0; j < 4; j++) {
            int row0 = bm + m0 + 16 * i + fr;
            int col  = bn + n0 + 8 * j + kp * 2;
            #pragma unroll
            for (int half = 0; half < 2; half++) {
                int row = row0 + half * 8;
                float v0 = acc[i][j][2 * half + 0];
                float v1 = acc[i][j][2 * half + 1];
                size_t off = (size_t)row * N + col;
                if (MODE == 0) {
                    *(float2*)(C + off) = make_float2(v0, v1);
                } else if (MODE == 1) {
                    float2 xr = *(const float2*)(X + off);
                    *(float2*)(C + off) = make_float2(v0 + xr.x, v1 + xr.y);
                } else {
                    float2 gr = *(const float2*)(X + off);
                    v0 *= gr.x / (1.0f + expf(-gr.x));
                    v1 *= gr.y / (1.0f + expf(-gr.y));
                    float h0, l0, h1, l1;
                    split1(v0, h0, l0);
                    split1(v1, h1, l1);
                    *(unsigned*)(Ch + off) = pack_bf2(h0, h1);
                    *(unsigned*)(Cl + off) = pack_bf2(l0, l1);
                }
            }
        }
    }
}

// ---------------- RoPE (in-place on fused qkv buffer) ----------------
__global__ void rope_kernel(const int* __restrict__ pos_ids) {
    int gid = blockIdx.x * blockDim.x + threadIdx.x;
    int d = gid & 31;
    int slot = gid >> 5;
    int head = slot % (NH + NKV);
    int tok = slot / (NH + NKV);
    if (tok >= M_TOK) return;
    float p = (float)pos_ids[tok];
    float inv = powf(10000.0f, -(float)d * (1.0f / 32.0f));
    float ang = p * inv;
    float s, c;
    sincosf(ang, &s, &c);
    float* base;
    if (head < NH) base = g_qkv + (size_t)tok * QKV_N + (head << 6);
    else           base = g_qkv + (size_t)tok * QKV_N + 2048 + ((head - NH) << 6);
    float x1 = base[d];
    float x2 = base[d + 32];
    base[d]      = x1 * c - x2 * s;
    base[d + 32] = x2 * c + x1 * s;
}

// ---------------- Tensor-core flash attention (causal, GQA) -> bf16 hi/lo planes ----------------
__global__ void __launch_bounds__(256, 2) attn_kernel() {
    extern __shared__ unsigned char smn[];
    unsigned sb = (unsigned)__cvta_generic_to_shared(smn);
    const unsigned QhO = 0,     QlO = 8192,  KhO = 16384, KlO = 24576;
    const unsigned VhO = 32768, VlO = 40960, PhO = 49152, PlO = 57344;
    float* St   = (float*)(smn + 65536);    // 64 x 68 fp32
    float* corr = (float*)(smn + 82944);    // 64
    float* linv = (float*)(smn + 83200);    // 64

    int qt = blockIdx.x, h = blockIdx.y, b = blockIdx.z;
    int kh = h >> 2;
    int tid = threadIdx.x, warp = tid >> 5, lane = tid & 31;
    int m0 = (warp >> 1) << 4;
    int n0 = (warp & 1) << 5;
    int lr = lane & 15, lc = lane >> 4;
    int fr = lane >> 2, kp = lane & 3;
    int qr = tid >> 2, qc = tid & 3;

    for (int i = tid; i < 1024; i += 256) {
        int r = i >> 4, c4 = (i & 15) << 2;
        const float* src = g_qkv + (size_t)(b*SEQ + (qt<<6) + r)*QKV_N + (h<<6) + c4;
        float4 q = *(const float4*)src;
        float h0,l0,h1,l1,h2,l2,h3,l3;
        split1(q.x*0.125f,h0,l0); split1(q.y*0.125f,h1,l1);
        split1(q.z*0.125f,h2,l2); split1(q.w*0.125f,h3,l3);
        unsigned off = SW128X(r*128 + c4*2);
        *(uint2*)(smn + QhO + off) = make_uint2(pack_bf2(h0,h1), pack_bf2(h2,h3));
        *(uint2*)(smn + QlO + off) = make_uint2(pack_bf2(l0,l1), pack_bf2(l2,l3));
    }

    float oacc[4][4];
    #pragma unroll
    for (int j = 0; j < 4; j++)
        #pragma unroll
        for (int r = 0; r < 4; r++) oacc[j][r] = 0.0f;
    float mrow = -INFINITY, lrow = 0.0f;

    for (int kt = 0; kt <= qt; kt++) {
        __syncthreads();
        int tokbase = b*SEQ + (kt<<6);
        for (int i = tid; i < 1024; i += 256) {
            int r = i >> 4, c4 = (i & 15) << 2;
            const float* ksrc = g_qkv + (size_t)(tokbase + r)*QKV_N + 2048 + (kh<<6) + c4;
            float4 kv = *(const float4*)ksrc;
            float4 vv = *(const float4*)(ksrc + 512);
            unsigned off = SW128X(r*128 + c4*2);
            float h0,l0,h1,l1,h2,l2,h3,l3;
            split1(kv.x,h0,l0); split1(kv.y,h1,l1); split1(kv.z,h2,l2); split1(kv.w,h3,l3);
            *(uint2*)(smn + KhO + off) = make_uint2(pack_bf2(h0,h1), pack_bf2(h2,h3));
            *(uint2*)(smn + KlO + off) = make_uint2(pack_bf2(l0,l1), pack_bf2(l2,l3));
            split1(vv.x,h0,l0); split1(vv.y,h1,l1); split1(vv.z,h2,l2); split1(vv.w,h3,l3);
            *(uint2*)(smn + VhO + off) = make_uint2(pack_bf2(h0,h1), pack_bf2(h2,h3));
            *(uint2*)(smn + VlO + off) = make_uint2(pack_bf2(l0,l1), pack_bf2(l2,l3));
        }
        __syncthreads();

        float accS[4][4];
        #pragma unroll
        for (int j = 0; j < 4; j++)
            #pragma unroll
            for (int r = 0; r < 4; r++) accS[j][r] = 0.0f;
        #pragma unroll
        for (int ks = 0; ks < 4; ks++) {
            unsigned co = 32*ks + 16*lc;
            unsigned aoff = SW128X((m0 + lr)*128 + co);
            unsigned ah[4], al[4];
            LDSM4(ah, sb + QhO + aoff);
            LDSM4(al, sb + QlO + aoff);
            #pragma unroll
            for (int j2 = 0; j2 < 2; j2++) {
                unsigned boff = SW128X((n0 + 16*j2 + lr)*128 + co);
                unsigned bh[4], bl[4];
                LDSM4(bh, sb + KhO + boff);
                LDSM4(bl, sb + KlO + boff);
                MMA_B16(accS[2*j2],   ah, bh[0], bh[2]);
                MMA_B16(accS[2*j2+1], ah, bh[1], bh[3]);
                MMA_B16(accS[2*j2],   ah, bl[0], bl[2]);
                MMA_B16(accS[2*j2+1], ah, bl[1], bl[3]);
                MMA_B16(accS[2*j2],   al, bh[0], bh[2]);
                MMA_B16(accS[2*j2+1], al, bh[1], bh[3]);
            }
        }
        bool diag = (kt == qt);
        #pragma unroll
        for (int j = 0; j < 4; j++) {
            int col = n0 + 8*j + 2*kp;
            #pragma unroll
            for (int hf = 0; hf < 2; hf++) {
                int row = m0 + fr + 8*hf;
                float v0 = accS[j][2*hf], v1 = accS[j][2*hf+1];
                if (diag) {
                    if (col > row)     v0 = -INFINITY;
                    if (col + 1 > row) v1 = -INFINITY;
                }
                *(float2*)&St[row*68 + col] = make_float2(v0, v1);
            }
        }
        __syncthreads();

        float* srow = &St[qr*68 + (qc<<4)];
        float tmax = -INFINITY;
        #pragma unroll
        for (int j = 0; j < 16; j++) tmax = fmaxf(tmax, srow[j]);
        tmax = fmaxf(tmax, __shfl_xor_sync(0xffffffffu, tmax, 1));
        tmax = fmaxf(tmax, __shfl_xor_sync(0xffffffffu, tmax, 2));
        float mnew = fmaxf(mrow, tmax);
        float cv = __expf(mrow - mnew);
        float psum = 0.0f;
        float pv[16];
        #pragma unroll
        for (int j = 0; j < 16; j++) { pv[j] = __expf(srow[j] - mnew); psum += pv[j]; }
        psum += __shfl_xor_sync(0xffffffffu, psum, 1);
        psum += __shfl_xor_sync(0xffffffffu, psum, 2);
        lrow = lrow * cv + psum;
        mrow = mnew;
        if (qc == 0) corr[qr] = cv;
        #pragma unroll
        for (int p = 0; p < 8; p++) {
            float hh0, ll0, hh1, ll1;
            split1(pv[2*p],   hh0, ll0);
            split1(pv[2*p+1], hh1, ll1);
            unsigned off = SW128X(qr*128 + qc*32 + p*4);
            *(unsigned*)(smn + PhO + off) = pack_bf2(hh0, hh1);
            *(unsigned*)(smn + PlO + off) = pack_bf2(ll0, ll1);
        }
        __syncthreads();

        float c0v = corr[m0 + fr], c1v = corr[m0 + fr + 8];
        #pragma unroll
        for (int j = 0; j < 4; j++) {
            oacc[j][0] *= c0v; oacc[j][1] *= c0v;
            oacc[j][2] *= c1v; oacc[j][3] *= c1v;
        }
        #pragma unroll
        for (int ks = 0; ks < 4; ks++) {
            unsigned co = 32*ks + 16*lc;
            unsigned aoff = SW128X((m0 + lr)*128 + co);
            unsigned ph[4], pl[4];
            LDSM4(ph, sb + PhO + aoff);
            LDSM4(pl, sb + PlO + aoff);
            #pragma unroll
            for (int j2 = 0; j2 < 2; j2++) {
                unsigned boff = SW128X((16*ks + lr)*128 + (n0 + 16*j2)*2 + 16*lc);
                unsigned bh[4], bl[4];
                LDSM4T(bh, sb + VhO + boff);
                LDSM4T(bl, sb + VlO + boff);
                MMA_B16(oacc[2*j2],   ph, bh[0], bh[1]);
                MMA_B16(oacc[2*j2+1], ph, bh[2], bh[3]);
                MMA_B16(oacc[2*j2],   ph, bl[0], bl[1]);
                MMA_B16(oacc[2*j2+1], ph, bl[2], bl[3]);
                MMA_B16(oacc[2*j2],   pl, bh[0], bh[1]);
                MMA_B16(oacc[2*j2+1], pl, bh[2], bh[3]);
            }
        }
    }

    if (qc == 0) linv[qr] = 1.0f / lrow;
    __syncthreads();
    float i0 = linv[m0 + fr], i1 = linv[m0 + fr + 8];
    #pragma unroll
    for (int j = 0; j < 4; j++) {
        int d = n0 + 8*j + 2*kp;
        #pragma unroll
        for (int hf = 0; hf < 2; hf++) {
            int row = m0 + fr + 8*hf;
            float sc = hf ? i1 : i0;
            float v0 = oacc[j][2*hf] * sc, v1 = oacc[j][2*hf+1] * sc;
            float h0, l0, h1, l1;
            split1(v0, h0, l0);
            split1(v1, h1, l1);
            size_t idx = (((size_t)(b*SEQ + (qt<<6) + row)*NH + h) << 6) + d;
            *(unsigned*)(g_ao_h + idx) = pack_bf2(h0, h1);
            *(unsigned*)(g_ao_l + idx) = pack_bf2(l0, l1);
        }
    }
}

// ---------------- launch ----------------
extern "C" void kernel_launch(void* const* d_in, const int* in_sizes, int n_in,
                              void* d_out, int out_size) {
    (void)in_sizes; (void)n_in; (void)out_size;
    const float* hs     = (const float*)d_in[0];
    const int*   pos    = (const int*)d_in[2];
    const float* q_w    = (const float*)d_in[3];
    const float* k_w    = (const float*)d_in[4];
    const float* v_w    = (const float*)d_in[5];
    const float* o_w    = (const float*)d_in[6];
    const float* gate_w = (const float*)d_in[7];
    const float* up_w   = (const float*)d_in[8];
    const float* down_w = (const float*)d_in[9];
    const float* ln1    = (const float*)d_in[10];
    const float* ln2    = (const float*)d_in[11];
    const float* kkp    = (const float*)d_in[12];
    const float* aap    = (const float*)d_in[13];
    float* out = (float*)d_out;

    float *qkv, *hid, *gate;
    __nv_bfloat16 *xnh, *xnl, *aoh, *aol, *acth, *actl, *wh, *wl;
    cudaGetSymbolAddress((void**)&qkv,  g_qkv);
    cudaGetSymbolAddress((void**)&hid,  g_hidden);
    cudaGetSymbolAddress((void**)&gate, g_gate);
    cudaGetSymbolAddress((void**)&xnh,  g_xn_h);
    cudaGetSymbolAddress((void**)&xnl,  g_xn_l);
    cudaGetSymbolAddress((void**)&aoh,  g_ao_h);
    cudaGetSymbolAddress((void**)&aol,  g_ao_l);
    cudaGetSymbolAddress((void**)&acth, g_act_h);
    cudaGetSymbolAddress((void**)&actl, g_act_l);
    cudaGetSymbolAddress((void**)&wh,   g_w_h);
    cudaGetSymbolAddress((void**)&wl,   g_w_l);

    cudaFuncSetAttribute(attn_kernel, cudaFuncAttributeMaxDynamicSharedMemorySize, ATTN_SMEM);
    cudaFuncSetAttribute(gemm_mma<0>, cudaFuncAttributeMaxDynamicSharedMemorySize, GEMM_SMEM);
    cudaFuncSetAttribute(gemm_mma<1>, cudaFuncAttributeMaxDynamicSharedMemorySize, GEMM_SMEM);
    cudaFuncSetAttribute(gemm_mma<2>, cudaFuncAttributeMaxDynamicSharedMemorySize, GEMM_SMEM);

    dim3 blk(256);

    // 0) weight prepass: binarize + bf16 split (Q,K,V planes contiguous)
    binsplit_kernel<<<(2048*2048)/1024, blk>>>(q_w,    wh + OFF_Q, wl + OFF_Q, kkp, aap);
    binsplit_kernel<<<(512*2048)/1024,  blk>>>(k_w,    wh + OFF_K, wl + OFF_K, kkp, aap);
    binsplit_kernel<<<(512*2048)/1024,  blk>>>(v_w,    wh + OFF_V, wl + OFF_V, kkp, aap);
    binsplit_kernel<<<(2048*2048)/1024, blk>>>(o_w,    wh + OFF_O, wl + OFF_O, kkp, aap);
    binsplit_kernel<<<(5632*2048)/1024, blk>>>(gate_w, wh + OFF_G, wl + OFF_G, kkp, aap);
    binsplit_kernel<<<(5632*2048)/1024, blk>>>(up_w,   wh + OFF_U, wl + OFF_U, kkp, aap);
    binsplit_kernel<<<(2048*5632)/1024, blk>>>(down_w, wh + OFF_D, wl + OFF_D, kkp, aap);

    // 1) rmsnorm 1 -> planes
    rmsnorm_kernel<<<M_TOK, blk>>>(hs, ln1, xnh, xnl);
    // 2) fused QKV projection (N = 3072)
    gemm_mma<0><<<dim3(QKV_N/128, M_TOK/128), blk, GEMM_SMEM>>>(xnh, xnl, wh+OFF_Q, wl+OFF_Q, nullptr, qkv, nullptr, nullptr, QKV_N, H);
    // 3) rope
    rope_kernel<<<(M_TOK*(NH+NKV)*32)/256, blk>>>(pos);
    // 4) attention -> ao planes
    attn_kernel<<<dim3(SEQ/64, NH, BATCH), blk, ATTN_SMEM>>>();
    // 5) o-proj + residual
    gemm_mma<1><<<dim3(H/128, M_TOK/128), blk, GEMM_SMEM>>>(aoh, aol, wh+OFF_O, wl+OFF_O, hs, hid, nullptr, nullptr, H, H);
    // 6) rmsnorm 2 -> planes
    rmsnorm_kernel<<<M_TOK, blk>>>(hid, ln2, xnh, xnl);
    // 7) gate proj (fp32 out)
    gemm_mma<0><<<dim3(FF/128, M_TOK/128), blk, GEMM_SMEM>>>(xnh, xnl, wh+OFF_G, wl+OFF_G, nullptr, gate, nullptr, nullptr, FF, H);
    // 8) up proj, fused silu(gate)*up -> act planes
    gemm_mma<2><<<dim3(FF/128, M_TOK/128), blk, GEMM_SMEM>>>(xnh, xnl, wh+OFF_U, wl+OFF_U, gate, nullptr, acth, actl, FF, H);
    // 9) down proj + residual -> out
    gemm_mma<1><<<dim3(H/128, M_TOK/128), blk, GEMM_SMEM>>>(acth, actl, wh+OFF_D, wl+OFF_D, hid, out, nullptr, nullptr, H, FF);
}